// round 15
// baseline (speedup 1.0000x reference)
#include <cuda_runtime.h>
#include <cuda_bf16.h>
#include <cuda_fp16.h>
#include <math.h>
#include <stdint.h>

#define NTOK 16384
#define CDIM 192
#define BATCH 8
#define NHEADS 8
#define HD 24

// gram config (triple-fused, fp16 single-term, merged (1,0), GCH=32) -- proven config
#define GSPLITK 8
#define GSLAB (NTOK / GSPLITK)  // 2048
#define GCH 32                  // k elems per chunk
#define GNCH (GSLAB / GCH)      // 64
#define SROW 40                 // padded smem row stride (fp16 elems)
#define RNG (96 * SROW)         // elems per plane
#define STG (4 * RNG)           // per stage (4 planes)
#define GRAM_SMEM (2 * STG * 2) // bytes (2 stages) = 61440

// out config (fp16 single-term: M and X single planes)
#define MROW 200
#define OXROW 136
#define XSTAGE (32 * OXROW)
#define OUT_SMEM (CDIM * MROW * 2 + 2 * XSTAGE * 2 + CDIM * 4)

// m_fused config
#define PROW 193  // odd stride: conflict-free column access
#define MF_SMEM (NHEADS * HD * HD * 4 + CDIM * PROW * 4)

// -------- scratch --------
__device__ float g_C[BATCH][6][CDIM][CDIM];
__device__ float g_s[BATCH][4][CDIM];  // rowsums: q1, x2, q2, x1
__device__ float g_T[BATCH][6][CDIM][CDIM];
__device__ float g_vec[BATCH][8][CDIM];
__device__ float g_attn[BATCH][2][NHEADS][HD][HD];
__device__ float g_tvec[BATCH][2][CDIM];
__device__ float g_cvec[BATCH][2][CDIM];
__device__ __half g_Mh[BATCH * 2][CDIM * CDIM];

// ================= mma helpers (sm_80-portable) =================
__device__ __forceinline__ uint32_t smem_u32(const void* p) {
    uint32_t a;
    asm("{ .reg .u64 t; cvta.to.shared.u64 t, %1; cvt.u32.u64 %0, t; }" : "=r"(a) : "l"(p));
    return a;
}
__device__ __forceinline__ void ldsm_x4(uint32_t* r, uint32_t addr) {
    asm volatile("ldmatrix.sync.aligned.m8n8.x4.shared.b16 {%0,%1,%2,%3}, [%4];"
                 : "=r"(r[0]), "=r"(r[1]), "=r"(r[2]), "=r"(r[3]) : "r"(addr));
}
__device__ __forceinline__ void ldsm_x4_t(uint32_t* r, uint32_t addr) {
    asm volatile("ldmatrix.sync.aligned.m8n8.x4.trans.shared.b16 {%0,%1,%2,%3}, [%4];"
                 : "=r"(r[0]), "=r"(r[1]), "=r"(r[2]), "=r"(r[3]) : "r"(addr));
}
// fp16 mma
__device__ __forceinline__ void mma16816h(float* d, const uint32_t* a, const uint32_t* b) {
    asm volatile(
        "mma.sync.aligned.m16n8k16.row.col.f32.f16.f16.f32 "
        "{%0,%1,%2,%3}, {%4,%5,%6,%7}, {%8,%9}, {%0,%1,%2,%3};"
        : "+f"(d[0]), "+f"(d[1]), "+f"(d[2]), "+f"(d[3])
        : "r"(a[0]), "r"(a[1]), "r"(a[2]), "r"(a[3]), "r"(b[0]), "r"(b[1]));
}
// fp16 packed store, hi only
__device__ __forceinline__ void cvt_store_h1(float4 v, __half* dh) {
    __half2 h01 = __floats2half2_rn(v.x, v.y);
    __half2 h23 = __floats2half2_rn(v.z, v.w);
    uint2 uh;
    uh.x = *(uint32_t*)&h01;
    uh.y = *(uint32_t*)&h23;
    *(uint2*)dh = uh;
}
__device__ __forceinline__ void atom4(float* C, int r, int c, const float* a) {
    atomicAdd(C + r * CDIM + c, a[0]);
    atomicAdd(C + r * CDIM + c + 1, a[1]);
    atomicAdd(C + (r + 8) * CDIM + c, a[2]);
    atomicAdd(C + (r + 8) * CDIM + c + 1, a[3]);
}
__device__ __forceinline__ void atom4t(float* C, int r, int c, const float* a) {
    atomicAdd(C + c * CDIM + r, a[0]);
    atomicAdd(C + (c + 1) * CDIM + r, a[1]);
    atomicAdd(C + c * CDIM + r + 8, a[2]);
    atomicAdd(C + (c + 1) * CDIM + r + 8, a[3]);
}

// ================= kernels =================
__global__ void zero_kernel() {
    size_t n = sizeof(g_C) / 4;
    float* c = &g_C[0][0][0][0];
    for (size_t i = (size_t)blockIdx.x * blockDim.x + threadIdx.x; i < n;
         i += (size_t)gridDim.x * blockDim.x)
        c[i] = 0.f;
    size_t ns = sizeof(g_s) / 4;
    float* s = &g_s[0][0][0];
    for (size_t i = (size_t)blockIdx.x * blockDim.x + threadIdx.x; i < ns;
         i += (size_t)gridDim.x * blockDim.x)
        s[i] = 0.f;
    size_t nv = sizeof(g_cvec) / 4;
    float* cv = &g_cvec[0][0][0];
    for (size_t i = (size_t)blockIdx.x * blockDim.x + threadIdx.x; i < nv;
         i += (size_t)gridDim.x * blockDim.x)
        cv[i] = 0.f;
}

// Triple-fused fp16 single-term gram with merged off-diagonal tile.
// cls 0: tile (0,0). cls 2: tile (1,1). cls 1: tile (0,1) + transposed + C2 (1,0).
// grid (GSPLITK, 3, BATCH*2), 384 threads (12 warps 2x6, warp 48x16/gram).
__global__ __launch_bounds__(384, 1) void gram_mma(const float* __restrict__ q1,
                                                   const float* __restrict__ q2,
                                                   const float* __restrict__ x1,
                                                   const float* __restrict__ x2) {
    extern __shared__ __align__(16) __half sm[];

    int sk = blockIdx.x, cls = blockIdx.y;
    int b = blockIdx.z >> 1, tr = blockIdx.z & 1;
    const float* A = (tr ? q2 : q1) + (size_t)b * CDIM * NTOK;
    const float* B = (tr ? x1 : x2) + (size_t)b * CDIM * NTOK;
    int slotA = tr ? 2 : 0, slotB = tr ? 3 : 1;
    float* C1 = &g_C[b][tr * 3 + 0][0][0];
    float* C2 = &g_C[b][tr * 3 + 1][0][0];
    float* C3 = &g_C[b][tr * 3 + 2][0][0];

    const float* lsrc[4];
    int larr[4], lslot[4], lrb[4], nld;
    if (cls == 1) {
        nld = 4;
        lsrc[0] = A; larr[0] = 0; lslot[0] = -1; lrb[0] = 0;
        lsrc[1] = A + (size_t)96 * NTOK; larr[1] = 1; lslot[1] = slotA; lrb[1] = 96;
        lsrc[2] = B; larr[2] = 2; lslot[2] = -1; lrb[2] = 0;
        lsrc[3] = B + (size_t)96 * NTOK; larr[3] = 3; lslot[3] = slotB; lrb[3] = 96;
    } else {
        nld = 2;
        size_t off = (cls == 2) ? (size_t)96 * NTOK : 0;
        lsrc[0] = A + off; larr[0] = 0; lslot[0] = (cls == 0) ? slotA : -1; lrb[0] = 0;
        lsrc[1] = B + off; larr[1] = 2; lslot[1] = (cls == 0) ? slotB : -1; lrb[1] = 0;
        lsrc[2] = lsrc[0]; larr[2] = 0; lslot[2] = -1; lrb[2] = 0;
        lsrc[3] = lsrc[0]; larr[3] = 0; lslot[3] = -1; lrb[3] = 0;
    }
    int jarr1 = (cls == 1) ? 1 : 0;
    int jarr3 = (cls == 1) ? 3 : 2;
    bool merged = (cls == 1);

    int tid = threadIdx.x, lane = tid & 31, wid = tid >> 5;
    int wm = wid / 6, wn = wid % 6;
    uint32_t smb = smem_u32(sm);

    float accC1[3][2][4] = {}, accC2[3][2][4] = {}, accC3[3][2][4] = {}, accC2b[3][2][4] = {};
    float rs[4] = {0.f, 0.f, 0.f, 0.f};

    int row = tid >> 2, c8 = (tid & 3) * 8;
    int kb0 = sk * GSLAB;

#pragma unroll
    for (int l = 0; l < 4; l++)
        if (l < nld) {
            const float* sp = lsrc[l] + (size_t)row * NTOK + kb0 + c8;
            float4 v0 = *(const float4*)sp;
            float4 v1 = *(const float4*)(sp + 4);
            if (lslot[l] >= 0)
                rs[l] += v0.x + v0.y + v0.z + v0.w + v1.x + v1.y + v1.z + v1.w;
            __half* dp = sm + larr[l] * RNG + row * SROW + c8;
            cvt_store_h1(v0, dp);
            cvt_store_h1(v1, dp + 4);
        }
    __syncthreads();

    float4 va[8];
    for (int ch = 0; ch < GNCH; ch++) {
        int cur = ch & 1, nxt = cur ^ 1;
        bool pf = (ch + 1 < GNCH);
        if (pf) {
            int kb = kb0 + (ch + 1) * GCH;
#pragma unroll
            for (int l = 0; l < 4; l++)
                if (l < nld) {
                    const float* sp = lsrc[l] + (size_t)row * NTOK + kb + c8;
                    va[2 * l] = *(const float4*)sp;
                    va[2 * l + 1] = *(const float4*)(sp + 4);
                }
        }

        uint32_t base = smb + cur * (STG * 2);
        int arow = wm * 48 + (lane & 15);
        int brow = wn * 16 + (lane & 7) + (((lane >> 4) & 1) << 3);
#pragma unroll
        for (int s = 0; s < 2; s++) {
            int acol = s * 16 + ((lane >> 4) << 3);
            int bcol = s * 16 + (((lane >> 3) & 1) << 3);

            uint32_t aih[12];
#pragma unroll
            for (int f = 0; f < 3; f++)
                ldsm_x4(aih + 4 * f, base + (uint32_t)(((arow + f * 16) * SROW + acol) * 2));
            uint32_t j1[4];
            ldsm_x4(j1, base + (uint32_t)((jarr1 * RNG + brow * SROW + bcol) * 2));
#pragma unroll
            for (int f = 0; f < 3; f++)
#pragma unroll
                for (int n = 0; n < 2; n++)
                    mma16816h(accC1[f][n], aih + 4 * f, j1 + 2 * n);
            uint32_t j3[4];
            ldsm_x4(j3, base + (uint32_t)((jarr3 * RNG + brow * SROW + bcol) * 2));
#pragma unroll
            for (int f = 0; f < 3; f++)
#pragma unroll
                for (int n = 0; n < 2; n++)
                    mma16816h(accC2[f][n], aih + 4 * f, j3 + 2 * n);
            uint32_t bih[12];
#pragma unroll
            for (int f = 0; f < 3; f++)
                ldsm_x4(bih + 4 * f,
                        base + (uint32_t)((2 * RNG + (arow + f * 16) * SROW + acol) * 2));
#pragma unroll
            for (int f = 0; f < 3; f++)
#pragma unroll
                for (int n = 0; n < 2; n++)
                    mma16816h(accC3[f][n], bih + 4 * f, j3 + 2 * n);
            if (merged) {
                uint32_t ai2[12], j2[4];
#pragma unroll
                for (int f = 0; f < 3; f++)
                    ldsm_x4(ai2 + 4 * f,
                            base + (uint32_t)((RNG + (arow + f * 16) * SROW + acol) * 2));
                ldsm_x4(j2, base + (uint32_t)((2 * RNG + brow * SROW + bcol) * 2));
#pragma unroll
                for (int f = 0; f < 3; f++)
#pragma unroll
                    for (int n = 0; n < 2; n++)
                        mma16816h(accC2b[f][n], ai2 + 4 * f, j2 + 2 * n);
            }
        }

        if (pf) {
            uint32_t nb = nxt * STG;
#pragma unroll
            for (int l = 0; l < 4; l++)
                if (l < nld) {
                    float4 v0 = va[2 * l], v1 = va[2 * l + 1];
                    if (lslot[l] >= 0)
                        rs[l] += v0.x + v0.y + v0.z + v0.w + v1.x + v1.y + v1.z + v1.w;
                    __half* dp = sm + nb + larr[l] * RNG + row * SROW + c8;
                    cvt_store_h1(v0, dp);
                    cvt_store_h1(v1, dp + 4);
                }
        }
        __syncthreads();
    }

    int ti = (cls == 2) ? 1 : 0;
    int tj = (cls == 0) ? 0 : 1;
    int rw = wm * 48 + (lane >> 2);
    int cw = wn * 16 + (lane & 3) * 2;
#pragma unroll
    for (int f = 0; f < 3; f++)
#pragma unroll
        for (int n = 0; n < 2; n++) {
            int r = ti * 96 + rw + f * 16, c = tj * 96 + cw + n * 8;
            atom4(C1, r, c, accC1[f][n]);
            atom4(C2, r, c, accC2[f][n]);
            atom4(C3, r, c, accC3[f][n]);
            if (merged) {
                atom4t(C1, r, c, accC1[f][n]);
                atom4t(C3, r, c, accC3[f][n]);
                atom4(C2, 96 + rw + f * 16, cw + n * 8, accC2b[f][n]);
            }
        }
#pragma unroll
    for (int l = 0; l < 4; l++)
        if (l < nld && lslot[l] >= 0) atomicAdd(&g_s[b][lslot[l]][lrb[l] + row], rs[l]);
}

// -------- small NN GEMMs (192x192x192): T = W @ C ; 64x64 tiles, 4x4/thread --------
__global__ void smallgemm_nn(const float* __restrict__ Wq, const float* __restrict__ Wk) {
    int z = blockIdx.z;
    int b = z / 6, g = z % 6;
    const float* W = (g == 2 || g == 5) ? Wk : Wq;
    const float* C = &g_C[b][g][0][0];
    float* D = &g_T[b][g][0][0];
    int m0 = blockIdx.y * 64, j0 = blockIdx.x * 64;
    __shared__ float Ws[32][68];  // 272B row stride (16B aligned)
    __shared__ float Cs[32][68];
    int t = threadIdx.x, tx = t % 16, ty = t / 16;
    float acc[4][4] = {};
    for (int k0 = 0; k0 < CDIM; k0 += 32) {
        __syncthreads();
        for (int e = t; e < 2048; e += 256) {
            int r = e >> 5, c = e & 31;
            Ws[c][r] = W[(m0 + r) * CDIM + k0 + c];
        }
        for (int e = t; e < 2048; e += 256) {
            int r = e >> 6, n = e & 63;
            Cs[r][n] = C[(k0 + r) * CDIM + j0 + n];
        }
        __syncthreads();
#pragma unroll
        for (int kk = 0; kk < 32; kk++) {
            float4 a4 = *(float4*)&Ws[kk][ty * 4];
            float4 b4 = *(float4*)&Cs[kk][tx * 4];
            float a[4] = {a4.x, a4.y, a4.z, a4.w};
            float bb[4] = {b4.x, b4.y, b4.z, b4.w};
#pragma unroll
            for (int i = 0; i < 4; i++)
#pragma unroll
                for (int j = 0; j < 4; j++) acc[i][j] = fmaf(a[i], bb[j], acc[i][j]);
        }
    }
#pragma unroll
    for (int i = 0; i < 4; i++)
#pragma unroll
        for (int j = 0; j < 4; j++)
            D[(m0 + ty * 4 + i) * CDIM + (j0 + tx * 4 + j)] = acc[i][j];
}

// -------- per-batch vectors (warp per (b,c)) --------
__global__ void vec_kernel(const float* __restrict__ Wq, const float* __restrict__ Wk,
                           const float* __restrict__ bq, const float* __restrict__ bk) {
    int c = blockIdx.x, b = blockIdx.y, l = threadIdx.x;
    float a0 = 0, a1 = 0, a2 = 0, a3 = 0, d0 = 0, d2 = 0, d3 = 0, d5 = 0;
    for (int i = l; i < CDIM; i += 32) {
        float wq = Wq[c * CDIM + i], wk = Wk[c * CDIM + i];
        a0 = fmaf(wq, g_s[b][0][i], a0);
        a1 = fmaf(wk, g_s[b][1][i], a1);
        a2 = fmaf(wq, g_s[b][2][i], a2);
        a3 = fmaf(wk, g_s[b][3][i], a3);
        d0 = fmaf(g_T[b][0][c][i], wq, d0);
        d2 = fmaf(g_T[b][2][c][i], wk, d2);
        d3 = fmaf(g_T[b][3][c][i], wq, d3);
        d5 = fmaf(g_T[b][5][c][i], wk, d5);
    }
#pragma unroll
    for (int s = 16; s > 0; s >>= 1) {
        a0 += __shfl_xor_sync(0xffffffff, a0, s);
        a1 += __shfl_xor_sync(0xffffffff, a1, s);
        a2 += __shfl_xor_sync(0xffffffff, a2, s);
        a3 += __shfl_xor_sync(0xffffffff, a3, s);
        d0 += __shfl_xor_sync(0xffffffff, d0, s);
        d2 += __shfl_xor_sync(0xffffffff, d2, s);
        d3 += __shfl_xor_sync(0xffffffff, d3, s);
        d5 += __shfl_xor_sync(0xffffffff, d5, s);
    }
    if (l == 0) {
        float bqc = bq[c], bkc = bk[c];
        const float NN = (float)NTOK;
        g_vec[b][0][c] = a0;
        g_vec[b][1][c] = a1;
        g_vec[b][2][c] = a2;
        g_vec[b][3][c] = a3;
        g_vec[b][4][c] = sqrtf(fmaxf(d0 + 2.f * bqc * a0 + NN * bqc * bqc, 0.f));
        g_vec[b][5][c] = sqrtf(fmaxf(d2 + 2.f * bkc * a1 + NN * bkc * bkc, 0.f));
        g_vec[b][6][c] = sqrtf(fmaxf(d3 + 2.f * bqc * a2 + NN * bqc * bqc, 0.f));
        g_vec[b][7][c] = sqrtf(fmaxf(d5 + 2.f * bkc * a3 + NN * bkc * bkc, 0.f));
    }
}

// -------- logits + softmax + fused cvec partial --------
__global__ void attn_kernel(const float* __restrict__ Wk, const float* __restrict__ bq,
                            const float* __restrict__ bk, const float* __restrict__ scale,
                            const float* __restrict__ bv, const float* __restrict__ Wproj) {
    int h = blockIdx.x, pair = blockIdx.y, b = blockIdx.z;
    __shared__ float sTA[HD][CDIM];
    __shared__ float sWk[HD][CDIM];
    __shared__ float slog[HD][HD];
    __shared__ float stv[HD];
    const float* TA = pair ? &g_T[b][4][0][0] : &g_T[b][1][0][0];
    const float* wqs = pair ? g_vec[b][2] : g_vec[b][0];
    const float* wks = pair ? g_vec[b][3] : g_vec[b][1];
    const float* nq = pair ? g_vec[b][6] : g_vec[b][4];
    const float* nk = pair ? g_vec[b][7] : g_vec[b][5];
    int t = threadIdx.x;
    for (int e = t; e < HD * CDIM; e += 256) {
        int r = e / CDIM, cc = e % CDIM;
        sTA[r][cc] = TA[(h * HD + r) * CDIM + cc];
        sWk[r][cc] = Wk[(h * HD + r) * CDIM + cc];
    }
    __syncthreads();
    float sc = scale[h];
    const float NN = (float)NTOK;
    for (int e = t; e < HD * HD; e += 256) {
        int i = e / HD, j = e % HD;
        int c = h * HD + i, d = h * HD + j;
        float dot = 0.f;
        for (int k = 0; k < CDIM; k++) dot = fmaf(sTA[i][k], sWk[j][k], dot);
        float raw = dot + wqs[c] * bk[d] + bq[c] * wks[d] + NN * bq[c] * bk[d];
        slog[i][j] = raw / (fmaxf(nq[c], 1e-12f) * fmaxf(nk[d], 1e-12f)) * sc;
    }
    __syncthreads();
    if (t < HD) {
        int i = t;
        float m = -INFINITY;
        for (int j = 0; j < HD; j++) m = fmaxf(m, slog[i][j]);
        float ex[HD];
        float sum = 0.f;
        for (int j = 0; j < HD; j++) { ex[j] = expf(slog[i][j] - m); sum += ex[j]; }
        float inv = 1.f / sum;
        float tv = 0.f;
        for (int j = 0; j < HD; j++) {
            float a = ex[j] * inv;
            g_attn[b][pair][h][i][j] = a;
            tv = fmaf(a, bv[h * HD + j], tv);
        }
        g_tvec[b][pair][h * HD + i] = tv;
        stv[i] = tv;
    }
    __syncthreads();
    // fused cvec partial: g_cvec[b][pair][c] += Wproj[c, h*HD : h*HD+HD] . stv
    if (t < CDIM) {
        float s = 0.f;
        const float* wrow = Wproj + t * CDIM + h * HD;
#pragma unroll
        for (int j = 0; j < HD; j++) s = fmaf(wrow[j], stv[j], s);
        atomicAdd(&g_cvec[b][pair][t], s);
    }
}

// -------- fused M = Wproj @ (BD(attn) @ Wv) -> g_Mh (fp16) --------
// grid (3, 2, BATCH), 512 threads; each block recomputes P in smem then its 64-row M slice.
__global__ __launch_bounds__(512, 1) void m_fused(const float* __restrict__ Wv,
                                                  const float* __restrict__ Wproj) {
    extern __shared__ __align__(16) float smf[];
    float* sA = smf;                         // [NHEADS*HD*HD] = 4608
    float* sP = smf + NHEADS * HD * HD;      // [CDIM][PROW]

    int mt = blockIdx.x, p = blockIdx.y, b = blockIdx.z;
    int t = threadIdx.x;
    const float* attnflat = &g_attn[b][p][0][0][0];
    for (int e = t; e < NHEADS * HD * HD; e += 512) sA[e] = attnflat[e];
    __syncthreads();

    // P[c][v] = sum_j attn[h(c)][i(c)][j] * Wv[h*HD+j][v]
    for (int e = t; e < CDIM * CDIM; e += 512) {
        int c = e / CDIM, v = e % CDIM;
        int h = c / HD, i = c % HD;
        const float* arow = sA + (h * HD + i) * HD;
        const float* wcol = Wv + (size_t)(h * HD) * CDIM + v;
        float acc = 0.f;
#pragma unroll
        for (int j = 0; j < HD; j++) acc = fmaf(arow[j], wcol[(size_t)j * CDIM], acc);
        sP[c * PROW + v] = acc;
    }
    __syncthreads();

    // M slice rows [mt*64, mt*64+64): M[m][v] = sum_c Wproj[m][c] * P[c][v]
    int m0 = mt * 64;
    __half* Dh = g_Mh[b * 2 + p];
    for (int e = t; e < 64 * CDIM; e += 512) {
        int mr = e / CDIM, v = e % CDIM;
        const float* wrow = Wproj + (size_t)(m0 + mr) * CDIM;
        float acc = 0.f;
        for (int c = 0; c < CDIM; c++) acc = fmaf(wrow[c], sP[c * PROW + v], acc);
        Dh[(m0 + mr) * CDIM + v] = __float2half(acc);
    }
}

// out = M @ X + cvec ; fp16 single-term: Mh x Xh.
__global__ __launch_bounds__(384, 1) void out_mma(const float* __restrict__ x1,
                                                  const float* __restrict__ x2,
                                                  float* __restrict__ out) {
    extern __shared__ __align__(16) __half smo[];
    __half* sM = smo;                       // [CDIM * MROW]
    __half* sX = smo + CDIM * MROW;         // stage s at s*XSTAGE
    float* scv = (float*)(smo + CDIM * MROW + 2 * XSTAGE);

    int z = blockIdx.y;
    int b = z >> 1, p = z & 1;
    const float* X = (p ? x1 : x2) + (size_t)b * CDIM * NTOK;
    const __half* Mh = g_Mh[z];
    float* O = out + (size_t)p * BATCH * CDIM * NTOK + (size_t)b * CDIM * NTOK;
    int n0 = blockIdx.x * 128;

    int tid = threadIdx.x, lane = tid & 31, wid = tid >> 5;
    int wm = wid >> 2, wn = wid & 3;

    if (tid < CDIM) scv[tid] = g_cvec[b][p][tid];

    for (int u = tid; u < CDIM * CDIM / 8; u += 384) {
        int row = u / 24, col = (u % 24) * 8;
        *(uint4*)(sM + row * MROW + col) = *(const uint4*)(Mh + row * CDIM + col);
    }
    for (int u = tid; u < 1024; u += 384) {
        int r = u >> 5, c4 = (u & 31) * 4;
        float4 v = *(const float4*)(X + (size_t)r * NTOK + n0 + c4);
        cvt_store_h1(v, sX + r * OXROW + c4);
    }
    __syncthreads();

    uint32_t sM_a = smem_u32(sM);
    uint32_t sX_a = smem_u32(sX);

    float acc[4][4][4];
#pragma unroll
    for (int i = 0; i < 4; i++)
#pragma unroll
        for (int j = 0; j < 4; j++)
#pragma unroll
            for (int k = 0; k < 4; k++) acc[i][j][k] = 0.f;

    float4 vx[3];
    for (int ch = 0; ch < 6; ch++) {
        int cur = ch & 1, nxt = cur ^ 1;
        bool pf = (ch < 5);
        if (pf) {
            int kb = (ch + 1) * 32;
#pragma unroll
            for (int it = 0; it < 3; it++) {
                int u = tid + it * 384;
                if (u < 1024) {
                    int r = u >> 5, c4 = (u & 31) * 4;
                    vx[it] = *(const float4*)(X + (size_t)(kb + r) * NTOK + n0 + c4);
                }
            }
        }

        uint32_t xb = sX_a + cur * (XSTAGE * 2);
#pragma unroll
        for (int s = 0; s < 2; s++) {
            int kg = ch * 32 + s * 16;
            uint32_t ah[16], bx[8];
            int arow0 = wm * 64 + (lane & 15);
            int acol = kg + ((lane >> 4) << 3);
#pragma unroll
            for (int i = 0; i < 4; i++)
                ldsm_x4(ah + 4 * i, sM_a + (uint32_t)(((arow0 + i * 16) * MROW + acol) * 2));
            int krow = s * 16 + (lane & 7) + (((lane >> 3) & 1) << 3);
            int ncol0 = wn * 32 + ((lane >> 4) << 3);
#pragma unroll
            for (int jb = 0; jb < 2; jb++)
                ldsm_x4_t(bx + 4 * jb, xb + (uint32_t)((krow * OXROW + ncol0 + jb * 16) * 2));
#pragma unroll
            for (int i = 0; i < 4; i++)
#pragma unroll
                for (int jj = 0; jj < 4; jj++)
                    mma16816h(acc[i][jj], ah + 4 * i, bx + (jj >> 1) * 4 + (jj & 1) * 2);
        }

        if (pf) {
            __half* nb = sX + nxt * XSTAGE;
#pragma unroll
            for (int it = 0; it < 3; it++) {
                int u = tid + it * 384;
                if (u < 1024) {
                    int r = u >> 5, c4 = (u & 31) * 4;
                    cvt_store_h1(vx[it], nb + r * OXROW + c4);
                }
            }
        }
        __syncthreads();
    }

    int r0 = wm * 64 + (lane >> 2);
    int nb = n0 + wn * 32 + (lane & 3) * 2;
#pragma unroll
    for (int i = 0; i < 4; i++) {
        int c = r0 + i * 16;
        float b0 = scv[c], b1 = scv[c + 8];
#pragma unroll
        for (int jj = 0; jj < 4; jj++) {
            float2 v0 = {acc[i][jj][0] + b0, acc[i][jj][1] + b0};
            float2 v1 = {acc[i][jj][2] + b1, acc[i][jj][3] + b1};
            *(float2*)(O + (size_t)c * NTOK + nb + jj * 8) = v0;
            *(float2*)(O + (size_t)(c + 8) * NTOK + nb + jj * 8) = v1;
        }
    }
}

extern "C" void kernel_launch(void* const* d_in, const int* in_sizes, int n_in,
                              void* d_out, int out_size) {
    const float* x1 = (const float*)d_in[0];
    const float* x2 = (const float*)d_in[1];
    const float* q1 = (const float*)d_in[2];
    const float* q2 = (const float*)d_in[3];
    const float* Wq = (const float*)d_in[4];
    const float* bq = (const float*)d_in[5];
    const float* Wk = (const float*)d_in[6];
    const float* bk = (const float*)d_in[7];
    const float* Wv = (const float*)d_in[8];
    const float* bv = (const float*)d_in[9];
    const float* scale = (const float*)d_in[10];
    const float* Wproj = (const float*)d_in[11];
    float* out = (float*)d_out;

    static int configured = 0;
    if (!configured) {
        cudaFuncSetAttribute(gram_mma, cudaFuncAttributeMaxDynamicSharedMemorySize, GRAM_SMEM);
        cudaFuncSetAttribute(out_mma, cudaFuncAttributeMaxDynamicSharedMemorySize, OUT_SMEM);
        cudaFuncSetAttribute(m_fused, cudaFuncAttributeMaxDynamicSharedMemorySize, MF_SMEM);
        configured = 1;
    }

    zero_kernel<<<256, 256>>>();
    gram_mma<<<dim3(GSPLITK, 3, BATCH * 2), 384, GRAM_SMEM>>>(q1, q2, x1, x2);
    smallgemm_nn<<<dim3(3, 3, BATCH * 6), 256>>>(Wq, Wk);
    vec_kernel<<<dim3(CDIM, BATCH), 32>>>(Wq, Wk, bq, bk);
    attn_kernel<<<dim3(NHEADS, 2, BATCH), 256>>>(Wk, bq, bk, scale, bv, Wproj);
    m_fused<<<dim3(3, 2, BATCH), 512, MF_SMEM>>>(Wv, Wproj);
    out_mma<<<dim3(NTOK / 128, BATCH * 2), 384, OUT_SMEM>>>(x1, x2, out);
}

// round 16
// speedup vs baseline: 1.1867x; 1.1867x over previous
#include <cuda_runtime.h>
#include <cuda_bf16.h>
#include <cuda_fp16.h>
#include <math.h>
#include <stdint.h>

#define NTOK 16384
#define CDIM 192
#define BATCH 8
#define NHEADS 8
#define HD 24

// gram config (triple-fused, fp16 single-term, merged (1,0), GCH=32) -- proven config
#define GSPLITK 8
#define GSLAB (NTOK / GSPLITK)  // 2048
#define GCH 32                  // k elems per chunk
#define GNCH (GSLAB / GCH)      // 64
#define SROW 40                 // padded smem row stride (fp16 elems)
#define RNG (96 * SROW)         // elems per plane
#define STG (4 * RNG)           // per stage (4 planes)
#define GRAM_SMEM (2 * STG * 2) // bytes (2 stages) = 61440

// out config (fp16 single-term: M and X single planes; 2 n-tiles per CTA)
#define MROW 200
#define OXROW 136
#define XSTAGE (32 * OXROW)
#define OUT_SMEM (CDIM * MROW * 2 + 2 * XSTAGE * 2 + CDIM * 4)

// -------- scratch --------
__device__ float g_C[BATCH][6][CDIM][CDIM];
__device__ float g_s[BATCH][4][CDIM];  // rowsums: q1, x2, q2, x1
__device__ float g_T[BATCH][6][CDIM][CDIM];
__device__ float g_vec[BATCH][8][CDIM];
__device__ float g_attn[BATCH][2][NHEADS][HD][HD];
__device__ float g_tvec[BATCH][2][CDIM];
__device__ float g_cvec[BATCH][2][CDIM];
__device__ float g_P[BATCH][2][CDIM][CDIM];
__device__ __half g_Mh[BATCH * 2][CDIM * CDIM];

// ================= mma helpers (sm_80-portable) =================
__device__ __forceinline__ uint32_t smem_u32(const void* p) {
    uint32_t a;
    asm("{ .reg .u64 t; cvta.to.shared.u64 t, %1; cvt.u32.u64 %0, t; }" : "=r"(a) : "l"(p));
    return a;
}
__device__ __forceinline__ void ldsm_x4(uint32_t* r, uint32_t addr) {
    asm volatile("ldmatrix.sync.aligned.m8n8.x4.shared.b16 {%0,%1,%2,%3}, [%4];"
                 : "=r"(r[0]), "=r"(r[1]), "=r"(r[2]), "=r"(r[3]) : "r"(addr));
}
__device__ __forceinline__ void ldsm_x4_t(uint32_t* r, uint32_t addr) {
    asm volatile("ldmatrix.sync.aligned.m8n8.x4.trans.shared.b16 {%0,%1,%2,%3}, [%4];"
                 : "=r"(r[0]), "=r"(r[1]), "=r"(r[2]), "=r"(r[3]) : "r"(addr));
}
// fp16 mma
__device__ __forceinline__ void mma16816h(float* d, const uint32_t* a, const uint32_t* b) {
    asm volatile(
        "mma.sync.aligned.m16n8k16.row.col.f32.f16.f16.f32 "
        "{%0,%1,%2,%3}, {%4,%5,%6,%7}, {%8,%9}, {%0,%1,%2,%3};"
        : "+f"(d[0]), "+f"(d[1]), "+f"(d[2]), "+f"(d[3])
        : "r"(a[0]), "r"(a[1]), "r"(a[2]), "r"(a[3]), "r"(b[0]), "r"(b[1]));
}
// fp16 packed store, hi only
__device__ __forceinline__ void cvt_store_h1(float4 v, __half* dh) {
    __half2 h01 = __floats2half2_rn(v.x, v.y);
    __half2 h23 = __floats2half2_rn(v.z, v.w);
    uint2 uh;
    uh.x = *(uint32_t*)&h01;
    uh.y = *(uint32_t*)&h23;
    *(uint2*)dh = uh;
}
__device__ __forceinline__ void atom4(float* C, int r, int c, const float* a) {
    atomicAdd(C + r * CDIM + c, a[0]);
    atomicAdd(C + r * CDIM + c + 1, a[1]);
    atomicAdd(C + (r + 8) * CDIM + c, a[2]);
    atomicAdd(C + (r + 8) * CDIM + c + 1, a[3]);
}
__device__ __forceinline__ void atom4t(float* C, int r, int c, const float* a) {
    atomicAdd(C + c * CDIM + r, a[0]);
    atomicAdd(C + (c + 1) * CDIM + r, a[1]);
    atomicAdd(C + c * CDIM + r + 8, a[2]);
    atomicAdd(C + (c + 1) * CDIM + r + 8, a[3]);
}

// ================= kernels =================
__global__ void zero_kernel() {
    size_t n = sizeof(g_C) / 4;
    float* c = &g_C[0][0][0][0];
    for (size_t i = (size_t)blockIdx.x * blockDim.x + threadIdx.x; i < n;
         i += (size_t)gridDim.x * blockDim.x)
        c[i] = 0.f;
    size_t ns = sizeof(g_s) / 4;
    float* s = &g_s[0][0][0];
    for (size_t i = (size_t)blockIdx.x * blockDim.x + threadIdx.x; i < ns;
         i += (size_t)gridDim.x * blockDim.x)
        s[i] = 0.f;
    size_t nv = sizeof(g_cvec) / 4;
    float* cv = &g_cvec[0][0][0];
    for (size_t i = (size_t)blockIdx.x * blockDim.x + threadIdx.x; i < nv;
         i += (size_t)gridDim.x * blockDim.x)
        cv[i] = 0.f;
}

// Triple-fused fp16 single-term gram with merged off-diagonal tile.
// grid (GSPLITK, 3, BATCH*2), 384 threads (12 warps 2x6, warp 48x16/gram).
__global__ __launch_bounds__(384, 1) void gram_mma(const float* __restrict__ q1,
                                                   const float* __restrict__ q2,
                                                   const float* __restrict__ x1,
                                                   const float* __restrict__ x2) {
    extern __shared__ __align__(16) __half sm[];

    int sk = blockIdx.x, cls = blockIdx.y;
    int b = blockIdx.z >> 1, tr = blockIdx.z & 1;
    const float* A = (tr ? q2 : q1) + (size_t)b * CDIM * NTOK;
    const float* B = (tr ? x1 : x2) + (size_t)b * CDIM * NTOK;
    int slotA = tr ? 2 : 0, slotB = tr ? 3 : 1;
    float* C1 = &g_C[b][tr * 3 + 0][0][0];
    float* C2 = &g_C[b][tr * 3 + 1][0][0];
    float* C3 = &g_C[b][tr * 3 + 2][0][0];

    const float* lsrc[4];
    int larr[4], lslot[4], lrb[4], nld;
    if (cls == 1) {
        nld = 4;
        lsrc[0] = A; larr[0] = 0; lslot[0] = -1; lrb[0] = 0;
        lsrc[1] = A + (size_t)96 * NTOK; larr[1] = 1; lslot[1] = slotA; lrb[1] = 96;
        lsrc[2] = B; larr[2] = 2; lslot[2] = -1; lrb[2] = 0;
        lsrc[3] = B + (size_t)96 * NTOK; larr[3] = 3; lslot[3] = slotB; lrb[3] = 96;
    } else {
        nld = 2;
        size_t off = (cls == 2) ? (size_t)96 * NTOK : 0;
        lsrc[0] = A + off; larr[0] = 0; lslot[0] = (cls == 0) ? slotA : -1; lrb[0] = 0;
        lsrc[1] = B + off; larr[1] = 2; lslot[1] = (cls == 0) ? slotB : -1; lrb[1] = 0;
        lsrc[2] = lsrc[0]; larr[2] = 0; lslot[2] = -1; lrb[2] = 0;
        lsrc[3] = lsrc[0]; larr[3] = 0; lslot[3] = -1; lrb[3] = 0;
    }
    int jarr1 = (cls == 1) ? 1 : 0;
    int jarr3 = (cls == 1) ? 3 : 2;
    bool merged = (cls == 1);

    int tid = threadIdx.x, lane = tid & 31, wid = tid >> 5;
    int wm = wid / 6, wn = wid % 6;
    uint32_t smb = smem_u32(sm);

    float accC1[3][2][4] = {}, accC2[3][2][4] = {}, accC3[3][2][4] = {}, accC2b[3][2][4] = {};
    float rs[4] = {0.f, 0.f, 0.f, 0.f};

    int row = tid >> 2, c8 = (tid & 3) * 8;
    int kb0 = sk * GSLAB;

#pragma unroll
    for (int l = 0; l < 4; l++)
        if (l < nld) {
            const float* sp = lsrc[l] + (size_t)row * NTOK + kb0 + c8;
            float4 v0 = *(const float4*)sp;
            float4 v1 = *(const float4*)(sp + 4);
            if (lslot[l] >= 0)
                rs[l] += v0.x + v0.y + v0.z + v0.w + v1.x + v1.y + v1.z + v1.w;
            __half* dp = sm + larr[l] * RNG + row * SROW + c8;
            cvt_store_h1(v0, dp);
            cvt_store_h1(v1, dp + 4);
        }
    __syncthreads();

    float4 va[8];
    for (int ch = 0; ch < GNCH; ch++) {
        int cur = ch & 1, nxt = cur ^ 1;
        bool pf = (ch + 1 < GNCH);
        if (pf) {
            int kb = kb0 + (ch + 1) * GCH;
#pragma unroll
            for (int l = 0; l < 4; l++)
                if (l < nld) {
                    const float* sp = lsrc[l] + (size_t)row * NTOK + kb + c8;
                    va[2 * l] = *(const float4*)sp;
                    va[2 * l + 1] = *(const float4*)(sp + 4);
                }
        }

        uint32_t base = smb + cur * (STG * 2);
        int arow = wm * 48 + (lane & 15);
        int brow = wn * 16 + (lane & 7) + (((lane >> 4) & 1) << 3);
#pragma unroll
        for (int s = 0; s < 2; s++) {
            int acol = s * 16 + ((lane >> 4) << 3);
            int bcol = s * 16 + (((lane >> 3) & 1) << 3);

            uint32_t aih[12];
#pragma unroll
            for (int f = 0; f < 3; f++)
                ldsm_x4(aih + 4 * f, base + (uint32_t)(((arow + f * 16) * SROW + acol) * 2));
            uint32_t j1[4];
            ldsm_x4(j1, base + (uint32_t)((jarr1 * RNG + brow * SROW + bcol) * 2));
#pragma unroll
            for (int f = 0; f < 3; f++)
#pragma unroll
                for (int n = 0; n < 2; n++)
                    mma16816h(accC1[f][n], aih + 4 * f, j1 + 2 * n);
            uint32_t j3[4];
            ldsm_x4(j3, base + (uint32_t)((jarr3 * RNG + brow * SROW + bcol) * 2));
#pragma unroll
            for (int f = 0; f < 3; f++)
#pragma unroll
                for (int n = 0; n < 2; n++)
                    mma16816h(accC2[f][n], aih + 4 * f, j3 + 2 * n);
            uint32_t bih[12];
#pragma unroll
            for (int f = 0; f < 3; f++)
                ldsm_x4(bih + 4 * f,
                        base + (uint32_t)((2 * RNG + (arow + f * 16) * SROW + acol) * 2));
#pragma unroll
            for (int f = 0; f < 3; f++)
#pragma unroll
                for (int n = 0; n < 2; n++)
                    mma16816h(accC3[f][n], bih + 4 * f, j3 + 2 * n);
            if (merged) {
                uint32_t ai2[12], j2[4];
#pragma unroll
                for (int f = 0; f < 3; f++)
                    ldsm_x4(ai2 + 4 * f,
                            base + (uint32_t)((RNG + (arow + f * 16) * SROW + acol) * 2));
                ldsm_x4(j2, base + (uint32_t)((2 * RNG + brow * SROW + bcol) * 2));
#pragma unroll
                for (int f = 0; f < 3; f++)
#pragma unroll
                    for (int n = 0; n < 2; n++)
                        mma16816h(accC2b[f][n], ai2 + 4 * f, j2 + 2 * n);
            }
        }

        if (pf) {
            uint32_t nb = nxt * STG;
#pragma unroll
            for (int l = 0; l < 4; l++)
                if (l < nld) {
                    float4 v0 = va[2 * l], v1 = va[2 * l + 1];
                    if (lslot[l] >= 0)
                        rs[l] += v0.x + v0.y + v0.z + v0.w + v1.x + v1.y + v1.z + v1.w;
                    __half* dp = sm + nb + larr[l] * RNG + row * SROW + c8;
                    cvt_store_h1(v0, dp);
                    cvt_store_h1(v1, dp + 4);
                }
        }
        __syncthreads();
    }

    int ti = (cls == 2) ? 1 : 0;
    int tj = (cls == 0) ? 0 : 1;
    int rw = wm * 48 + (lane >> 2);
    int cw = wn * 16 + (lane & 3) * 2;
#pragma unroll
    for (int f = 0; f < 3; f++)
#pragma unroll
        for (int n = 0; n < 2; n++) {
            int r = ti * 96 + rw + f * 16, c = tj * 96 + cw + n * 8;
            atom4(C1, r, c, accC1[f][n]);
            atom4(C2, r, c, accC2[f][n]);
            atom4(C3, r, c, accC3[f][n]);
            if (merged) {
                atom4t(C1, r, c, accC1[f][n]);
                atom4t(C3, r, c, accC3[f][n]);
                atom4(C2, 96 + rw + f * 16, cw + n * 8, accC2b[f][n]);
            }
        }
#pragma unroll
    for (int l = 0; l < 4; l++)
        if (l < nld && lslot[l] >= 0) atomicAdd(&g_s[b][lslot[l]][lrb[l] + row], rs[l]);
}

// -------- small NN GEMMs (192x192x192): D = W @ C ; 64x64 tiles, 4x4/thread --------
__global__ void smallgemm_nn(const float* __restrict__ Wq, const float* __restrict__ Wk,
                             const float* __restrict__ Wproj, int mode) {
    int z = blockIdx.z;
    const float* W; const float* C; float* D = nullptr;
    __half* Dh = nullptr;
    if (mode == 0) {
        int b = z / 6, g = z % 6;
        W = (g == 2 || g == 5) ? Wk : Wq;
        C = &g_C[b][g][0][0];
        D = &g_T[b][g][0][0];
    } else {
        int b = z / 2, p = z % 2;
        W = Wproj;
        C = &g_P[b][p][0][0];
        Dh = g_Mh[z];
        (void)b;
    }
    int m0 = blockIdx.y * 64, j0 = blockIdx.x * 64;
    __shared__ float Ws[32][68];  // 272B row stride (16B aligned)
    __shared__ float Cs[32][68];
    int t = threadIdx.x, tx = t % 16, ty = t / 16;
    float acc[4][4] = {};
    for (int k0 = 0; k0 < CDIM; k0 += 32) {
        __syncthreads();
        for (int e = t; e < 2048; e += 256) {
            int r = e >> 5, c = e & 31;
            Ws[c][r] = W[(m0 + r) * CDIM + k0 + c];
        }
        for (int e = t; e < 2048; e += 256) {
            int r = e >> 6, n = e & 63;
            Cs[r][n] = C[(k0 + r) * CDIM + j0 + n];
        }
        __syncthreads();
#pragma unroll
        for (int kk = 0; kk < 32; kk++) {
            float4 a4 = *(float4*)&Ws[kk][ty * 4];
            float4 b4 = *(float4*)&Cs[kk][tx * 4];
            float a[4] = {a4.x, a4.y, a4.z, a4.w};
            float bb[4] = {b4.x, b4.y, b4.z, b4.w};
#pragma unroll
            for (int i = 0; i < 4; i++)
#pragma unroll
                for (int j = 0; j < 4; j++) acc[i][j] = fmaf(a[i], bb[j], acc[i][j]);
        }
    }
    if (mode == 0) {
#pragma unroll
        for (int i = 0; i < 4; i++)
#pragma unroll
            for (int j = 0; j < 4; j++)
                D[(m0 + ty * 4 + i) * CDIM + (j0 + tx * 4 + j)] = acc[i][j];
    } else {
#pragma unroll
        for (int i = 0; i < 4; i++)
#pragma unroll
            for (int j = 0; j < 4; j++)
                Dh[(m0 + ty * 4 + i) * CDIM + (j0 + tx * 4 + j)] = __float2half(acc[i][j]);
    }
}

// -------- per-batch vectors (warp per (b,c)) --------
__global__ void vec_kernel(const float* __restrict__ Wq, const float* __restrict__ Wk,
                           const float* __restrict__ bq, const float* __restrict__ bk) {
    int c = blockIdx.x, b = blockIdx.y, l = threadIdx.x;
    float a0 = 0, a1 = 0, a2 = 0, a3 = 0, d0 = 0, d2 = 0, d3 = 0, d5 = 0;
    for (int i = l; i < CDIM; i += 32) {
        float wq = Wq[c * CDIM + i], wk = Wk[c * CDIM + i];
        a0 = fmaf(wq, g_s[b][0][i], a0);
        a1 = fmaf(wk, g_s[b][1][i], a1);
        a2 = fmaf(wq, g_s[b][2][i], a2);
        a3 = fmaf(wk, g_s[b][3][i], a3);
        d0 = fmaf(g_T[b][0][c][i], wq, d0);
        d2 = fmaf(g_T[b][2][c][i], wk, d2);
        d3 = fmaf(g_T[b][3][c][i], wq, d3);
        d5 = fmaf(g_T[b][5][c][i], wk, d5);
    }
#pragma unroll
    for (int s = 16; s > 0; s >>= 1) {
        a0 += __shfl_xor_sync(0xffffffff, a0, s);
        a1 += __shfl_xor_sync(0xffffffff, a1, s);
        a2 += __shfl_xor_sync(0xffffffff, a2, s);
        a3 += __shfl_xor_sync(0xffffffff, a3, s);
        d0 += __shfl_xor_sync(0xffffffff, d0, s);
        d2 += __shfl_xor_sync(0xffffffff, d2, s);
        d3 += __shfl_xor_sync(0xffffffff, d3, s);
        d5 += __shfl_xor_sync(0xffffffff, d5, s);
    }
    if (l == 0) {
        float bqc = bq[c], bkc = bk[c];
        const float NN = (float)NTOK;
        g_vec[b][0][c] = a0;
        g_vec[b][1][c] = a1;
        g_vec[b][2][c] = a2;
        g_vec[b][3][c] = a3;
        g_vec[b][4][c] = sqrtf(fmaxf(d0 + 2.f * bqc * a0 + NN * bqc * bqc, 0.f));
        g_vec[b][5][c] = sqrtf(fmaxf(d2 + 2.f * bkc * a1 + NN * bkc * bkc, 0.f));
        g_vec[b][6][c] = sqrtf(fmaxf(d3 + 2.f * bqc * a2 + NN * bqc * bqc, 0.f));
        g_vec[b][7][c] = sqrtf(fmaxf(d5 + 2.f * bkc * a3 + NN * bkc * bkc, 0.f));
    }
}

// -------- logits + softmax + fused cvec partial --------
__global__ void attn_kernel(const float* __restrict__ Wk, const float* __restrict__ bq,
                            const float* __restrict__ bk, const float* __restrict__ scale,
                            const float* __restrict__ bv, const float* __restrict__ Wproj) {
    int h = blockIdx.x, pair = blockIdx.y, b = blockIdx.z;
    __shared__ float sTA[HD][CDIM];
    __shared__ float sWk[HD][CDIM];
    __shared__ float slog[HD][HD];
    __shared__ float stv[HD];
    const float* TA = pair ? &g_T[b][4][0][0] : &g_T[b][1][0][0];
    const float* wqs = pair ? g_vec[b][2] : g_vec[b][0];
    const float* wks = pair ? g_vec[b][3] : g_vec[b][1];
    const float* nq = pair ? g_vec[b][6] : g_vec[b][4];
    const float* nk = pair ? g_vec[b][7] : g_vec[b][5];
    int t = threadIdx.x;
    for (int e = t; e < HD * CDIM; e += 256) {
        int r = e / CDIM, cc = e % CDIM;
        sTA[r][cc] = TA[(h * HD + r) * CDIM + cc];
        sWk[r][cc] = Wk[(h * HD + r) * CDIM + cc];
    }
    __syncthreads();
    float sc = scale[h];
    const float NN = (float)NTOK;
    for (int e = t; e < HD * HD; e += 256) {
        int i = e / HD, j = e % HD;
        int c = h * HD + i, d = h * HD + j;
        float dot = 0.f;
        for (int k = 0; k < CDIM; k++) dot = fmaf(sTA[i][k], sWk[j][k], dot);
        float raw = dot + wqs[c] * bk[d] + bq[c] * wks[d] + NN * bq[c] * bk[d];
        slog[i][j] = raw / (fmaxf(nq[c], 1e-12f) * fmaxf(nk[d], 1e-12f)) * sc;
    }
    __syncthreads();
    if (t < HD) {
        int i = t;
        float m = -INFINITY;
        for (int j = 0; j < HD; j++) m = fmaxf(m, slog[i][j]);
        float ex[HD];
        float sum = 0.f;
        for (int j = 0; j < HD; j++) { ex[j] = expf(slog[i][j] - m); sum += ex[j]; }
        float inv = 1.f / sum;
        float tv = 0.f;
        for (int j = 0; j < HD; j++) {
            float a = ex[j] * inv;
            g_attn[b][pair][h][i][j] = a;
            tv = fmaf(a, bv[h * HD + j], tv);
        }
        g_tvec[b][pair][h * HD + i] = tv;
        stv[i] = tv;
    }
    __syncthreads();
    // fused cvec partial: g_cvec[b][pair][c] += Wproj[c, h*HD : h*HD+HD] . stv
    if (t < CDIM) {
        float s = 0.f;
        const float* wrow = Wproj + t * CDIM + h * HD;
#pragma unroll
        for (int j = 0; j < HD; j++) s = fmaf(wrow[j], stv[j], s);
        atomicAdd(&g_cvec[b][pair][t], s);
    }
}

__global__ void p_kernel(const float* __restrict__ Wv) {
    int vt = blockIdx.x, p = blockIdx.y, b = blockIdx.z;
    int v0 = vt * 32;
    __shared__ float sA[NHEADS][HD][HD];
    __shared__ float sWv[CDIM][32];
    int t = threadIdx.x;
    const float* attnflat = &g_attn[b][p][0][0][0];
    for (int e = t; e < NHEADS * HD * HD; e += 256) (&sA[0][0][0])[e] = attnflat[e];
    for (int e = t; e < CDIM * 32; e += 256) {
        int r = e / 32, vc = e % 32;
        sWv[r][vc] = Wv[r * CDIM + v0 + vc];
    }
    __syncthreads();
    for (int e = t; e < CDIM * 32; e += 256) {
        int c = e / 32, vc = e % 32;
        int h = c / HD, i = c % HD;
        float acc = 0.f;
#pragma unroll
        for (int j = 0; j < HD; j++) acc = fmaf(sA[h][i][j], sWv[h * HD + j][vc], acc);
        g_P[b][p][c][v0 + vc] = acc;
    }
}

// out = M @ X + cvec ; fp16 single-term. M resident, reused across 2 n-tiles.
// grid (NTOK/256, 16), 384 threads.
__global__ __launch_bounds__(384, 1) void out_mma(const float* __restrict__ x1,
                                                  const float* __restrict__ x2,
                                                  float* __restrict__ out) {
    extern __shared__ __align__(16) __half smo[];
    __half* sM = smo;                       // [CDIM * MROW]
    __half* sX = smo + CDIM * MROW;         // stage s at s*XSTAGE
    float* scv = (float*)(smo + CDIM * MROW + 2 * XSTAGE);

    int z = blockIdx.y;
    int b = z >> 1, p = z & 1;
    const float* X = (p ? x1 : x2) + (size_t)b * CDIM * NTOK;
    const __half* Mh = g_Mh[z];
    float* O = out + (size_t)p * BATCH * CDIM * NTOK + (size_t)b * CDIM * NTOK;

    int tid = threadIdx.x, lane = tid & 31, wid = tid >> 5;
    int wm = wid >> 2, wn = wid & 3;

    if (tid < CDIM) scv[tid] = g_cvec[b][p][tid];
    // resident M load (once)
    for (int u = tid; u < CDIM * CDIM / 8; u += 384) {
        int row = u / 24, col = (u % 24) * 8;
        *(uint4*)(sM + row * MROW + col) = *(const uint4*)(Mh + row * CDIM + col);
    }

    uint32_t sM_a = smem_u32(sM);
    uint32_t sX_a = smem_u32(sX);

#pragma unroll 1
    for (int tile = 0; tile < 2; tile++) {
        int n0 = (blockIdx.x * 2 + tile) * 128;

        __syncthreads();  // M/scv visible (tile 0); prior tile's sX reads done (tile 1)
        for (int u = tid; u < 1024; u += 384) {
            int r = u >> 5, c4 = (u & 31) * 4;
            float4 v = *(const float4*)(X + (size_t)r * NTOK + n0 + c4);
            cvt_store_h1(v, sX + r * OXROW + c4);
        }
        __syncthreads();

        float acc[4][4][4];
#pragma unroll
        for (int i = 0; i < 4; i++)
#pragma unroll
            for (int j = 0; j < 4; j++)
#pragma unroll
                for (int k = 0; k < 4; k++) acc[i][j][k] = 0.f;

        float4 vx[3];
        for (int ch = 0; ch < 6; ch++) {
            int cur = ch & 1, nxt = cur ^ 1;
            bool pf = (ch < 5);
            if (pf) {
                int kb = (ch + 1) * 32;
#pragma unroll
                for (int it = 0; it < 3; it++) {
                    int u = tid + it * 384;
                    if (u < 1024) {
                        int r = u >> 5, c4 = (u & 31) * 4;
                        vx[it] = *(const float4*)(X + (size_t)(kb + r) * NTOK + n0 + c4);
                    }
                }
            }

            uint32_t xb = sX_a + cur * (XSTAGE * 2);
#pragma unroll
            for (int s = 0; s < 2; s++) {
                int kg = ch * 32 + s * 16;
                uint32_t ah[16], bx[8];
                int arow0 = wm * 64 + (lane & 15);
                int acol = kg + ((lane >> 4) << 3);
#pragma unroll
                for (int i = 0; i < 4; i++)
                    ldsm_x4(ah + 4 * i,
                            sM_a + (uint32_t)(((arow0 + i * 16) * MROW + acol) * 2));
                int krow = s * 16 + (lane & 7) + (((lane >> 3) & 1) << 3);
                int ncol0 = wn * 32 + ((lane >> 4) << 3);
#pragma unroll
                for (int jb = 0; jb < 2; jb++)
                    ldsm_x4_t(bx + 4 * jb,
                              xb + (uint32_t)((krow * OXROW + ncol0 + jb * 16) * 2));
#pragma unroll
                for (int i = 0; i < 4; i++)
#pragma unroll
                    for (int jj = 0; jj < 4; jj++)
                        mma16816h(acc[i][jj], ah + 4 * i, bx + (jj >> 1) * 4 + (jj & 1) * 2);
            }

            if (pf) {
                __half* nb = sX + nxt * XSTAGE;
#pragma unroll
                for (int it = 0; it < 3; it++) {
                    int u = tid + it * 384;
                    if (u < 1024) {
                        int r = u >> 5, c4 = (u & 31) * 4;
                        cvt_store_h1(vx[it], nb + r * OXROW + c4);
                    }
                }
            }
            __syncthreads();
        }

        int r0 = wm * 64 + (lane >> 2);
        int nb2 = n0 + wn * 32 + (lane & 3) * 2;
#pragma unroll
        for (int i = 0; i < 4; i++) {
            int c = r0 + i * 16;
            float b0 = scv[c], b1 = scv[c + 8];
#pragma unroll
            for (int jj = 0; jj < 4; jj++) {
                float2 v0 = {acc[i][jj][0] + b0, acc[i][jj][1] + b0};
                float2 v1 = {acc[i][jj][2] + b1, acc[i][jj][3] + b1};
                *(float2*)(O + (size_t)c * NTOK + nb2 + jj * 8) = v0;
                *(float2*)(O + (size_t)(c + 8) * NTOK + nb2 + jj * 8) = v1;
            }
        }
    }
}

extern "C" void kernel_launch(void* const* d_in, const int* in_sizes, int n_in,
                              void* d_out, int out_size) {
    const float* x1 = (const float*)d_in[0];
    const float* x2 = (const float*)d_in[1];
    const float* q1 = (const float*)d_in[2];
    const float* q2 = (const float*)d_in[3];
    const float* Wq = (const float*)d_in[4];
    const float* bq = (const float*)d_in[5];
    const float* Wk = (const float*)d_in[6];
    const float* bk = (const float*)d_in[7];
    const float* Wv = (const float*)d_in[8];
    const float* bv = (const float*)d_in[9];
    const float* scale = (const float*)d_in[10];
    const float* Wproj = (const float*)d_in[11];
    float* out = (float*)d_out;

    static int configured = 0;
    if (!configured) {
        cudaFuncSetAttribute(gram_mma, cudaFuncAttributeMaxDynamicSharedMemorySize, GRAM_SMEM);
        cudaFuncSetAttribute(out_mma, cudaFuncAttributeMaxDynamicSharedMemorySize, OUT_SMEM);
        configured = 1;
    }

    zero_kernel<<<256, 256>>>();
    gram_mma<<<dim3(GSPLITK, 3, BATCH * 2), 384, GRAM_SMEM>>>(q1, q2, x1, x2);
    smallgemm_nn<<<dim3(3, 3, BATCH * 6), 256>>>(Wq, Wk, Wproj, 0);
    vec_kernel<<<dim3(CDIM, BATCH), 32>>>(Wq, Wk, bq, bk);
    attn_kernel<<<dim3(NHEADS, 2, BATCH), 256>>>(Wk, bq, bk, scale, bv, Wproj);
    p_kernel<<<dim3(6, 2, BATCH), 256>>>(Wv);
    smallgemm_nn<<<dim3(3, 3, BATCH * 2), 256>>>(Wq, Wk, Wproj, 1);
    out_mma<<<dim3(NTOK / 256, BATCH * 2), 384, OUT_SMEM>>>(x1, x2, out);
}